// round 3
// baseline (speedup 1.0000x reference)
#include <cuda_runtime.h>
#include <cstdint>

#define NB 12
#define DM 128
#define NH 2
#define HD 64

typedef unsigned long long u64;

struct Consts {
    float ta[NH];            // alpha' (scaled by log2e/sqrt(hd))
    float tb[NH][NB];        // beta'
    float gam[NH][NB];       // gamma'
    float del[NH][NB][NB];   // delta'
    float u[NH];             // va_h . Wo_h
    float w[NH][NB];         // vc[k,h] . Wo_h
    float bo;
};

__device__ Consts g_c;
__device__ float g_av[3][DM];          // qa, ka, va
__device__ float g_cv[3][NB][DM];      // qc[b], kc[b], vc[b]

__device__ __forceinline__ float ex2f(float v) {
    float y;
    asm("ex2.approx.f32 %0, %1;" : "=f"(y) : "f"(v));
    return y;
}
__device__ __forceinline__ u64 pk(float lo, float hi) {
    u64 r; asm("mov.b64 %0, {%1, %2};" : "=l"(r) : "f"(lo), "f"(hi)); return r;
}
__device__ __forceinline__ float2 upk(u64 v) {
    float2 r; asm("mov.b64 {%0, %1}, %2;" : "=f"(r.x), "=f"(r.y) : "l"(v)); return r;
}
__device__ __forceinline__ u64 fma2(u64 a, u64 b, u64 c) {
    u64 d; asm("fma.rn.f32x2 %0, %1, %2, %3;" : "=l"(d) : "l"(a), "l"(b), "l"(c)); return d;
}
__device__ __forceinline__ u64 add2(u64 a, u64 b) {
    u64 d; asm("add.rn.f32x2 %0, %1, %2;" : "=l"(d) : "l"(a), "l"(b)); return d;
}
__device__ __forceinline__ float warp_sum(float v) {
    v += __shfl_xor_sync(0xffffffffu, v, 16);
    v += __shfl_xor_sync(0xffffffffu, v, 8);
    v += __shfl_xor_sync(0xffffffffu, v, 4);
    v += __shfl_xor_sync(0xffffffffu, v, 2);
    v += __shfl_xor_sync(0xffffffffu, v, 1);
    return v;
}

// ---------------------------------------------------------------------------
// Setup 1: one WARP per length-128 dot product (4992 warps total).
// ---------------------------------------------------------------------------
__global__ __launch_bounds__(128) void spec_setup1(
        const float* __restrict__ we, const float* __restrict__ be,
        const float* __restrict__ bp,
        const float* __restrict__ Wq, const float* __restrict__ bq,
        const float* __restrict__ Wk, const float* __restrict__ bk,
        const float* __restrict__ Wv, const float* __restrict__ bv) {
    int gw = (blockIdx.x * blockDim.x + threadIdx.x) >> 5;
    int lane = threadIdx.x & 31;
    if (gw >= 3 * 13 * DM) return;
    int m = gw / (13 * DM);
    int r = gw % (13 * DM);
    int v = r / DM;
    int i = r % DM;
    const float* W  = (m == 0) ? Wq : (m == 1) ? Wk : Wv;
    const float* bb = (m == 0) ? bq : (m == 1) ? bk : bv;

    float4 rw = ((const float4*)(W + i * DM))[lane];
    float partial;
    if (v == 0) {
        float4 e = ((const float4*)we)[lane];
        partial = rw.x * e.x + rw.y * e.y + rw.z * e.z + rw.w * e.w;
    } else {
        float4 e = ((const float4*)be)[lane];
        float4 p = ((const float4*)(bp + (v - 1) * DM))[lane];
        partial = rw.x * (e.x + p.x) + rw.y * (e.y + p.y)
                + rw.z * (e.z + p.z) + rw.w * (e.w + p.w);
    }
    float s = warp_sum(partial);
    if (lane == 0) {
        if (v == 0) g_av[m][i] = s;
        else        g_cv[m][v - 1][i] = s + bb[i];
    }
}

// ---------------------------------------------------------------------------
// Setup 2: one WARP per length-64 dot product (365 warps).
// ---------------------------------------------------------------------------
__global__ __launch_bounds__(256) void spec_setup2(const float* __restrict__ Wo,
                                                   const float* __restrict__ bo) {
    int gw = (blockIdx.x * blockDim.x + threadIdx.x) >> 5;
    int lane = threadIdx.x & 31;
    const float cfac = 0.125f * 1.4426950408889634f;

    if (gw >= NH * 182) {
        if (gw == NH * 182 && lane == 0) g_c.bo = bo[0];
        return;
    }
    int h = gw / 182;
    int t = gw % 182;
    int off = h * HD;

    const float* a; const float* b; float* dst; float sc = cfac;
    if (t == 0)       { a = &g_av[0][off]; b = &g_av[1][off]; dst = &g_c.ta[h]; }
    else if (t == 1)  { a = &g_av[2][off]; b = Wo + off; dst = &g_c.u[h]; sc = 1.0f; }
    else if (t < 14)  { int bd = t - 2;  a = &g_av[0][off]; b = &g_cv[1][bd][off]; dst = &g_c.tb[h][bd]; }
    else if (t < 26)  { int bd = t - 14; a = &g_cv[0][bd][off]; b = &g_av[1][off]; dst = &g_c.gam[h][bd]; }
    else if (t < 38)  { int bd = t - 26; a = &g_cv[2][bd][off]; b = Wo + off; dst = &g_c.w[h][bd]; sc = 1.0f; }
    else {
        int idx = t - 38, q = idx / NB, k = idx % NB;
        a = &g_cv[0][q][off]; b = &g_cv[1][k][off]; dst = &g_c.del[h][q][k];
    }
    float2 av = ((const float2*)a)[lane];
    float2 bv = ((const float2*)b)[lane];
    float s = warp_sum(av.x * bv.x + av.y * bv.y);
    if (lane == 0) *dst = s * sc;
}

// ---------------------------------------------------------------------------
// Main kernel: one thread per token, softmax rows processed in PAIRS using
// packed fma.rn.f32x2. exp split between MUFU (ex2.approx, 8/12 k's) and
// the fma pipe (deg-5 Taylor of 2^s, 4/12 k's) to balance pipe load.
// ---------------------------------------------------------------------------
__global__ __launch_bounds__(128) void spec_main(const float* __restrict__ x,
                                                 float* __restrict__ out, int N) {
    __shared__ float2 sDel2[NH][NB / 2][NB];   // (del[2q2][k], del[2q2+1][k])
    __shared__ float2 sGam2[NH][NB / 2];
    __shared__ float sTa[NH], sU[NH], sBo;
    __shared__ float sTb[NH][NB], sW[NH][NB];

    {
        int td = threadIdx.x;
        for (int i = td; i < NH * (NB / 2) * NB; i += blockDim.x) {
            int h = i / ((NB / 2) * NB);
            int r = i % ((NB / 2) * NB);
            int q2 = r / NB, k = r % NB;
            sDel2[h][q2][k] = make_float2(g_c.del[h][2 * q2][k], g_c.del[h][2 * q2 + 1][k]);
        }
        if (td < NH * (NB / 2)) {
            int h = td / (NB / 2), q2 = td % (NB / 2);
            sGam2[h][q2] = make_float2(g_c.gam[h][2 * q2], g_c.gam[h][2 * q2 + 1]);
        }
        if (td < NH * NB) {
            int h = td / NB, k = td % NB;
            sTb[h][k] = g_c.tb[h][k];
            sW[h][k]  = g_c.w[h][k];
        }
        if (td < NH) { sTa[td] = g_c.ta[td]; sU[td] = g_c.u[td]; }
        if (td == 0) sBo = g_c.bo;
    }
    __syncthreads();

    int n = blockIdx.x * blockDim.x + threadIdx.x;
    if (n >= N) return;

    const float4* xp = (const float4*)(x + (size_t)n * NB);
    float4 a0 = xp[0], a1 = xp[1], a2 = xp[2];
    float xv[NB] = {a0.x, a0.y, a0.z, a0.w, a1.x, a1.y, a1.z, a1.w,
                    a2.x, a2.y, a2.z, a2.w};

    // packed duplicated x (for the k side)
    u64 xd2[NB];
    #pragma unroll
    for (int k = 0; k < NB; k++) xd2[k] = pk(xv[k], xv[k]);

    // deg-5 Taylor coefficients for 2^s = e^{s ln2}
    const float L = 0.6931471805599453f;
    const u64 C1 = pk(L, L);
    const u64 C2 = pk(L * L * 0.5f, L * L * 0.5f);
    const u64 C3 = pk(L * L * L / 6.0f, L * L * L / 6.0f);
    const u64 C4 = pk(L * L * L * L / 24.0f, L * L * L * L / 24.0f);
    const u64 C5 = pk(L * L * L * L * L / 120.0f, L * L * L * L * L / 120.0f);
    const u64 ONE = pk(1.0f, 1.0f);

    float delta[NB];
    #pragma unroll
    for (int q = 0; q < NB; q++) delta[q] = sBo;

    #pragma unroll
    for (int h = 0; h < NH; h++) {
        float ah = sTa[h], uh = sU[h];
        u64 t2[NB], m2[NB];
        #pragma unroll
        for (int k = 0; k < NB; k++) {
            float tk = fmaf(xv[k], ah, sTb[h][k]);
            float mk = fmaf(xv[k], uh, sW[h][k]);
            t2[k] = pk(tk, tk);
            m2[k] = pk(mk, mk);
        }
        #pragma unroll
        for (int q2 = 0; q2 < NB / 2; q2++) {
            u64 g2  = *(const u64*)&sGam2[h][q2];
            u64 xq2 = pk(xv[2 * q2], xv[2 * q2 + 1]);
            u64 rs = pk(0.f, 0.f), ds = pk(0.f, 0.f);
            #pragma unroll
            for (int k = 0; k < NB; k++) {
                u64 del2 = *(const u64*)&sDel2[h][q2][k];
                u64 s2 = fma2(xq2, t2[k], fma2(xd2[k], g2, del2));
                u64 e2;
                if (k < 4) {
                    u64 p = fma2(s2, C5, C4);
                    p = fma2(s2, p, C3);
                    p = fma2(s2, p, C2);
                    p = fma2(s2, p, C1);
                    e2 = fma2(s2, p, ONE);
                } else {
                    float2 sf = upk(s2);
                    e2 = pk(ex2f(sf.x), ex2f(sf.y));
                }
                rs = add2(rs, e2);
                ds = fma2(e2, m2[k], ds);
            }
            float2 rsf = upk(rs), dsf = upk(ds);
            delta[2 * q2]     += __fdividef(dsf.x, rsf.x);
            delta[2 * q2 + 1] += __fdividef(dsf.y, rsf.y);
        }
    }

    float4 o0 = make_float4(xv[0] + delta[0], xv[1] + delta[1], xv[2] + delta[2], xv[3] + delta[3]);
    float4 o1 = make_float4(xv[4] + delta[4], xv[5] + delta[5], xv[6] + delta[6], xv[7] + delta[7]);
    float4 o2 = make_float4(xv[8] + delta[8], xv[9] + delta[9], xv[10] + delta[10], xv[11] + delta[11]);
    float4* op = (float4*)(out + (size_t)n * NB);
    op[0] = o0; op[1] = o1; op[2] = o2;
}

// ---------------------------------------------------------------------------
extern "C" void kernel_launch(void* const* d_in, const int* in_sizes, int n_in,
                              void* d_out, int out_size) {
    const float* x  = (const float*)d_in[0];
    const float* we = (const float*)d_in[1];
    const float* be = (const float*)d_in[2];
    const float* bp = (const float*)d_in[3];
    const float* Wq = (const float*)d_in[4];
    const float* bq = (const float*)d_in[5];
    const float* Wk = (const float*)d_in[6];
    const float* bk = (const float*)d_in[7];
    const float* Wv = (const float*)d_in[8];
    const float* bv = (const float*)d_in[9];
    const float* Wo = (const float*)d_in[10];
    const float* bo = (const float*)d_in[11];
    float* out = (float*)d_out;

    int N = in_sizes[0] / NB;  // 65536 tokens

    int s1_warps = 3 * 13 * DM;                 // 4992 warps
    spec_setup1<<<(s1_warps + 3) / 4, 128>>>(we, be, bp, Wq, bq, Wk, bk, Wv, bv);

    int s2_warps = NH * 182 + 1;                // 365 warps
    spec_setup2<<<(s2_warps + 7) / 8, 256>>>(Wo, bo);

    spec_main<<<(N + 127) / 128, 128>>>(x, out, N);
}